// round 10
// baseline (speedup 1.0000x reference)
#include <cuda_runtime.h>
#include <cuda_fp16.h>
#include <cstdint>

#define NN   50000
#define EE   800000
#define HIN  256
#define HH   128
#define BNEPS 1e-5f

// ---------------- device scratch ----------------
__device__ int    g_degr[NN];
__device__ int    g_cnt[NN];
__device__ int    g_cursor[NN];
__device__ int    g_startv[NN + 1];
__device__ int    g_csr_rows[EE];
__device__ float  g_dinv[NN];
__device__ __half g_s[(size_t)NN * HH];      // pre-aggregation messages (fp16, UNSCALED)
__device__ __half g_ah[(size_t)NN * HIN];    // A operand hi (fp16)
__device__ __half g_al[(size_t)NN * HIN];    // A operand lo (fp16)
__device__ __half g_w16[HH * HIN];           // folded weight fp16, [n][k] K-major
__device__ float  g_sum[HIN];
__device__ float  g_sumsq[HIN];
__device__ float  g_bshift[HH];

// ---------------- PTX helpers (baseline sm_80+ only) ----------------
__device__ __forceinline__ uint32_t smem_u32(const void* p) {
    uint32_t a;
    asm("{ .reg .u64 t; cvta.to.shared.u64 t, %1; cvt.u32.u64 %0, t; }" : "=r"(a) : "l"(p));
    return a;
}
#define CP16(dst, src) \
    asm volatile("cp.async.cg.shared.global [%0], [%1], 16;" :: "r"(dst), "l"(src))
#define CP_COMMIT() asm volatile("cp.async.commit_group;" ::: "memory")
#define CP_WAIT1()  asm volatile("cp.async.wait_group 1;" ::: "memory")
#define LDSM_X4(r, addr) \
    asm volatile("ldmatrix.sync.aligned.m8n8.x4.shared.b16 {%0,%1,%2,%3}, [%4];" \
        : "=r"((r)[0]), "=r"((r)[1]), "=r"((r)[2]), "=r"((r)[3]) : "r"(addr))
#define MMA_F16(c, a, b) \
    asm volatile("mma.sync.aligned.m16n8k16.row.col.f32.f16.f16.f32 " \
        "{%0,%1,%2,%3}, {%4,%5,%6,%7}, {%8,%9}, {%0,%1,%2,%3};" \
        : "+f"((c)[0]), "+f"((c)[1]), "+f"((c)[2]), "+f"((c)[3]) \
        : "r"((a)[0]), "r"((a)[1]), "r"((a)[2]), "r"((a)[3]), "r"((b)[0]), "r"((b)[1]))

// ---------------- CSR build ----------------
__global__ void k_zero_counts() {
    int i = blockIdx.x * blockDim.x + threadIdx.x;
    if (i < NN) { g_degr[i] = 0; g_cnt[i] = 0; g_cursor[i] = 0; }
}
__global__ void k_count(const int* __restrict__ ei) {
    int e = blockIdx.x * blockDim.x + threadIdx.x;
    if (e < EE) {
        atomicAdd(&g_degr[ei[e]], 1);
        atomicAdd(&g_cnt[ei[EE + e]], 1);
    }
}
__global__ void k_scan() {
    __shared__ int part[1024];
    int t = threadIdx.x;
    const int per = (NN + 1023) / 1024;
    int b = t * per, e = min(b + per, NN);
    int s = 0;
    for (int i = b; i < e; i++) s += g_cnt[i];
    part[t] = s;
    __syncthreads();
    for (int off = 1; off < 1024; off <<= 1) {
        int v = (t >= off) ? part[t - off] : 0;
        __syncthreads();
        part[t] += v;
        __syncthreads();
    }
    int base = (t == 0) ? 0 : part[t - 1];
    for (int i = b; i < e; i++) { g_startv[i] = base; base += g_cnt[i]; }
    if (t == 1023) g_startv[NN] = part[1023];
}
__global__ void k_fill(const int* __restrict__ ei) {
    int e = blockIdx.x * blockDim.x + threadIdx.x;
    if (e < EE) {
        int r = ei[e], c = ei[EE + e];
        int p = atomicAdd(&g_cursor[c], 1);
        g_csr_rows[g_startv[c] + p] = r;
    }
}
__global__ void k_dinv() {
    int i = blockIdx.x * blockDim.x + threadIdx.x;
    if (i < NN) g_dinv[i] = rsqrtf((float)g_degr[i] + 1.0f);
}

// ---------------- BN stats for raw input x (K=256) ----------------
__global__ void k_stats(const float* __restrict__ A, int C) {
    int j = threadIdx.x;
    int r0 = blockIdx.x * 128;
    int rend = min(r0 + 128, NN);
    float s = 0.f, ss = 0.f;
    for (int r = r0; r < rend; r++) {
        float v = A[(size_t)r * C + j];
        s += v; ss += v * v;
    }
    atomicAdd(&g_sum[j], s);
    atomicAdd(&g_sumsq[j], ss);
}

// ---------------- fold BN into weights; emit fp16 W^T + fp32 bshift ----------------
__global__ void k_fold(int K, const float* __restrict__ W,
                       const float* __restrict__ gam, const float* __restrict__ bet) {
    __shared__ float sc[HIN], sh[HIN];
    int t = threadIdx.x;             // 256 threads
    if (t < K) {
        float mu  = g_sum[t] * (1.0f / NN);
        float var = g_sumsq[t] * (1.0f / NN) - mu * mu;
        float a   = rsqrtf(var + BNEPS) * gam[t];
        sc[t] = a;
        sh[t] = bet[t] - mu * a;
    }
    __syncthreads();
    for (int idx = t; idx < K * HH; idx += 256) {
        int k = idx >> 7;            // W row
        int n = idx & 127;           // W col
        g_w16[(size_t)n * K + k] = __float2half_rn(sc[k] * W[idx]);
    }
    if (t < HH) {
        float acc = 0.f;
        for (int k = 0; k < K; k++) acc += sh[k] * W[k * HH + t];
        g_bshift[t] = acc;
    }
    g_sum[t] = 0.f;
    g_sumsq[t] = 0.f;
}

// ---------------- split raw x -> fp16 hi/lo ----------------
__global__ void k_convx(const float* __restrict__ x) {
    size_t i = (size_t)blockIdx.x * blockDim.x + threadIdx.x;   // over NN*HIN/4
    float4 v = ((const float4*)x)[i];
    __half h0 = __float2half_rn(v.x), h1 = __float2half_rn(v.y);
    __half h2 = __float2half_rn(v.z), h3 = __float2half_rn(v.w);
    __half2* ph = (__half2*)g_ah;
    __half2* pl = (__half2*)g_al;
    ph[i * 2 + 0] = __halves2half2(h0, h1);
    ph[i * 2 + 1] = __halves2half2(h2, h3);
    pl[i * 2 + 0] = __floats2half2_rn(v.x - __half2float(h0), v.y - __half2float(h1));
    pl[i * 2 + 1] = __floats2half2_rn(v.z - __half2float(h2), v.w - __half2float(h3));
}

// ---------------- 2-term fp16 HMMA GEMM ----------------
// g_s(fp16) = (Ah + Al) @ W16^T + bshift        (NO dinv here — moved to gather)
#define RS   48
#define TSZ  (128 * RS)          // 6144 bytes per tile
#define STG  (3 * TSZ)           // 18432 bytes per stage

__global__ void __launch_bounds__(256) k_gemm_h(int K) {
    __shared__ char smem[2 * STG];
    const int t    = threadIdx.x;
    const int wid  = t >> 5;
    const int lane = t & 31;
    const int wm   = wid & 3;          // 32-row band
    const int wn   = wid >> 2;         // 64-col band
    const int row0 = blockIdx.x * 128;
    const uint32_t sbase = smem_u32(smem);

    float c[2][8][4];
    #pragma unroll
    for (int mt = 0; mt < 2; mt++)
        #pragma unroll
        for (int nt = 0; nt < 8; nt++)
            #pragma unroll
            for (int q = 0; q < 4; q++) c[mt][nt][q] = 0.f;

    const int lr = t >> 1;
    const int lh = t & 1;
    const int ar = min(row0 + lr, NN - 1);
    const uint32_t so = lr * RS + lh * 16;
    const int nch = K >> 4;

    {
        size_t ka = (size_t)ar * K + lh * 8;
        size_t kb = (size_t)lr * K + lh * 8;
        CP16(sbase + 0 * TSZ + so, g_ah + ka);
        CP16(sbase + 1 * TSZ + so, g_al + ka);
        CP16(sbase + 2 * TSZ + so, g_w16 + kb);
    }
    CP_COMMIT();

    for (int kc = 0; kc < nch; kc++) {
        if (kc + 1 < nch) {
            uint32_t sb = sbase + ((kc + 1) & 1) * STG;
            size_t ka = (size_t)ar * K + (kc + 1) * 16 + lh * 8;
            size_t kb = (size_t)lr * K + (kc + 1) * 16 + lh * 8;
            CP16(sb + 0 * TSZ + so, g_ah + ka);
            CP16(sb + 1 * TSZ + so, g_al + ka);
            CP16(sb + 2 * TSZ + so, g_w16 + kb);
        }
        CP_COMMIT();
        CP_WAIT1();
        __syncthreads();

        uint32_t base = sbase + (kc & 1) * STG;
        uint32_t ah[2][4], al[2][4];
        #pragma unroll
        for (int mt = 0; mt < 2; mt++) {
            uint32_t addr = base + (wm * 32 + mt * 16 + (lane & 15)) * RS + (lane >> 4) * 16;
            LDSM_X4(ah[mt], addr);
            LDSM_X4(al[mt], addr + TSZ);
        }
        uint32_t bw[8][2];
        #pragma unroll
        for (int p = 0; p < 4; p++) {
            uint32_t addr = base + 2 * TSZ + (wn * 64 + p * 16 + (lane & 15)) * RS + (lane >> 4) * 16;
            uint32_t rr[4];
            LDSM_X4(rr, addr);
            bw[2 * p][0] = rr[0]; bw[2 * p][1] = rr[2];
            bw[2 * p + 1][0] = rr[1]; bw[2 * p + 1][1] = rr[3];
        }
        #pragma unroll
        for (int mt = 0; mt < 2; mt++)
            #pragma unroll
            for (int nt = 0; nt < 8; nt++) {
                MMA_F16(c[mt][nt], ah[mt], bw[nt]);
                MMA_F16(c[mt][nt], al[mt], bw[nt]);
            }
        __syncthreads();
    }

    // epilogue: acc + bshift[col] -> fp16 g_s (unscaled)
    float bsv[8][2];
    #pragma unroll
    for (int nt = 0; nt < 8; nt++) {
        int gc = wn * 64 + nt * 8 + (lane & 3) * 2;
        bsv[nt][0] = __ldg(&g_bshift[gc]);
        bsv[nt][1] = __ldg(&g_bshift[gc + 1]);
    }
    #pragma unroll
    for (int mt = 0; mt < 2; mt++) {
        int r0g = row0 + wm * 32 + mt * 16 + (lane >> 2);
        int r1g = r0g + 8;
        #pragma unroll
        for (int nt = 0; nt < 8; nt++) {
            int gc = wn * 64 + nt * 8 + (lane & 3) * 2;
            if (r0g < NN)
                *(__half2*)(g_s + (size_t)r0g * HH + gc) =
                    __floats2half2_rn(c[mt][nt][0] + bsv[nt][0],
                                      c[mt][nt][1] + bsv[nt][1]);
            if (r1g < NN)
                *(__half2*)(g_s + (size_t)r1g * HH + gc) =
                    __floats2half2_rn(c[mt][nt][2] + bsv[nt][0],
                                      c[mt][nt][3] + bsv[nt][1]);
        }
    }
}

// ---------------- gather:  out[c] = dinv_c*(Σ s'_r*dinv_r + s'_c*dinv_c) + b ----------------
__global__ void __launch_bounds__(256) k_gather(const float* __restrict__ bgcn,
                                                float* __restrict__ out, int final_layer) {
    const int lane = threadIdx.x & 31;
    const int wg   = (blockIdx.x * blockDim.x + threadIdx.x) >> 5;
    const int nw   = (gridDim.x * blockDim.x) >> 5;
    __shared__ float sS[128], sQ[128];
    if (threadIdx.x < 128) { sS[threadIdx.x] = 0.f; sQ[threadIdx.x] = 0.f; }
    __syncthreads();

    const uint2* __restrict__ s2 = (const uint2*)g_s;   // 32 uint2 per row
    float4 b = *(const float4*)(bgcn + lane * 4);
    float4 stS = make_float4(0.f, 0.f, 0.f, 0.f);
    float4 stQ = make_float4(0.f, 0.f, 0.f, 0.f);

    for (int node = wg; node < NN; node += nw) {
        float dvn = __ldg(&g_dinv[node]);
        uint2 vs = s2[(size_t)node * 32 + lane];        // self-loop (scaled by dvn)
        float2 f0 = __half22float2(*(__half2*)&vs.x);
        float2 f1 = __half22float2(*(__half2*)&vs.y);
        float4 A0 = make_float4(f0.x * dvn, f0.y * dvn, f1.x * dvn, f1.y * dvn);
        float4 A1 = make_float4(0.f, 0.f, 0.f, 0.f);
        float4 A2 = make_float4(0.f, 0.f, 0.f, 0.f);
        float4 A3 = make_float4(0.f, 0.f, 0.f, 0.f);

        int beg = g_startv[node];
        int end = g_startv[node + 1];
        int k = beg;
        for (; k + 3 < end; k += 4) {
            int r0 = __ldg(&g_csr_rows[k]);
            int r1 = __ldg(&g_csr_rows[k + 1]);
            int r2 = __ldg(&g_csr_rows[k + 2]);
            int r3 = __ldg(&g_csr_rows[k + 3]);
            float d0 = __ldg(&g_dinv[r0]);
            float d1 = __ldg(&g_dinv[r1]);
            float d2 = __ldg(&g_dinv[r2]);
            float d3 = __ldg(&g_dinv[r3]);
            uint2 v0 = s2[(size_t)r0 * 32 + lane];
            uint2 v1 = s2[(size_t)r1 * 32 + lane];
            uint2 v2 = s2[(size_t)r2 * 32 + lane];
            uint2 v3 = s2[(size_t)r3 * 32 + lane];
            float2 p0 = __half22float2(*(__half2*)&v0.x);
            float2 p1 = __half22float2(*(__half2*)&v0.y);
            A0.x += p0.x * d0; A0.y += p0.y * d0; A0.z += p1.x * d0; A0.w += p1.y * d0;
            p0 = __half22float2(*(__half2*)&v1.x);
            p1 = __half22float2(*(__half2*)&v1.y);
            A1.x += p0.x * d1; A1.y += p0.y * d1; A1.z += p1.x * d1; A1.w += p1.y * d1;
            p0 = __half22float2(*(__half2*)&v2.x);
            p1 = __half22float2(*(__half2*)&v2.y);
            A2.x += p0.x * d2; A2.y += p0.y * d2; A2.z += p1.x * d2; A2.w += p1.y * d2;
            p0 = __half22float2(*(__half2*)&v3.x);
            p1 = __half22float2(*(__half2*)&v3.y);
            A3.x += p0.x * d3; A3.y += p0.y * d3; A3.z += p1.x * d3; A3.w += p1.y * d3;
        }
        for (; k < end; k++) {
            int r0 = __ldg(&g_csr_rows[k]);
            float d0 = __ldg(&g_dinv[r0]);
            uint2 v0 = s2[(size_t)r0 * 32 + lane];
            float2 p0 = __half22float2(*(__half2*)&v0.x);
            float2 p1 = __half22float2(*(__half2*)&v0.y);
            A0.x += p0.x * d0; A0.y += p0.y * d0; A0.z += p1.x * d0; A0.w += p1.y * d0;
        }
        float4 o;
        o.x = (A0.x + A1.x + A2.x + A3.x) * dvn + b.x;
        o.y = (A0.y + A1.y + A2.y + A3.y) * dvn + b.y;
        o.z = (A0.z + A1.z + A2.z + A3.z) * dvn + b.z;
        o.w = (A0.w + A1.w + A2.w + A3.w) * dvn + b.w;

        if (final_layer) {
            *(float4*)(out + (size_t)node * HH + lane * 4) = o;
        } else {
            __half h0 = __float2half_rn(o.x), h1 = __float2half_rn(o.y);
            __half h2 = __float2half_rn(o.z), h3 = __float2half_rn(o.w);
            size_t base = (size_t)node * HH + lane * 4;
            __half2* ph = (__half2*)(g_ah + base);
            __half2* pl = (__half2*)(g_al + base);
            ph[0] = __halves2half2(h0, h1);
            ph[1] = __halves2half2(h2, h3);
            pl[0] = __floats2half2_rn(o.x - __half2float(h0), o.y - __half2float(h1));
            pl[1] = __floats2half2_rn(o.z - __half2float(h2), o.w - __half2float(h3));
            stS.x += o.x; stS.y += o.y; stS.z += o.z; stS.w += o.w;
            stQ.x += o.x * o.x; stQ.y += o.y * o.y;
            stQ.z += o.z * o.z; stQ.w += o.w * o.w;
        }
    }

    if (!final_layer) {
        atomicAdd(&sS[lane * 4 + 0], stS.x);
        atomicAdd(&sS[lane * 4 + 1], stS.y);
        atomicAdd(&sS[lane * 4 + 2], stS.z);
        atomicAdd(&sS[lane * 4 + 3], stS.w);
        atomicAdd(&sQ[lane * 4 + 0], stQ.x);
        atomicAdd(&sQ[lane * 4 + 1], stQ.y);
        atomicAdd(&sQ[lane * 4 + 2], stQ.z);
        atomicAdd(&sQ[lane * 4 + 3], stQ.w);
        __syncthreads();
        if (threadIdx.x < 128) {
            atomicAdd(&g_sum[threadIdx.x], sS[threadIdx.x]);
            atomicAdd(&g_sumsq[threadIdx.x], sQ[threadIdx.x]);
        }
    }
}

// ---------------- launch ----------------
extern "C" void kernel_launch(void* const* d_in, const int* in_sizes, int n_in,
                              void* d_out, int out_size) {
    const float* x       = (const float*)d_in[0];
    const int*   ei      = (const int*)  d_in[1];
    const float* bnf_g   = (const float*)d_in[2];
    const float* bnf_b   = (const float*)d_in[3];
    const float* W_feat  = (const float*)d_in[4];
    const float* b_feat  = (const float*)d_in[5];
    const float* bn_g    = (const float*)d_in[6];
    const float* bn_b    = (const float*)d_in[7];
    const float* Ws      = (const float*)d_in[8];
    const float* bs      = (const float*)d_in[9];
    float* out = (float*)d_out;

    const int RB = (NN + 127) / 128;              // 391 tiles
    const int GB = 782;
    const int EB = (EE + 255) / 256;

    // GEMM chain first (no dinv dependency anymore) -> k_gemm_h is launch #3 (ncu window)
    k_stats<<<RB, HIN>>>(x, HIN);                    // 0
    k_fold<<<1, 256>>>(HIN, W_feat, bnf_g, bnf_b);   // 1
    k_convx<<<(NN * HIN / 4 + 255) / 256, 256>>>(x); // 2
    k_gemm_h<<<RB, 256>>>(HIN);                      // 3  <- profiled
    // CSR chain
    k_zero_counts<<<(NN + 255) / 256, 256>>>();      // 4
    k_count<<<EB, 256>>>(ei);                        // 5
    k_dinv<<<(NN + 255) / 256, 256>>>();             // 6
    k_scan<<<1, 1024>>>();                           // 7
    k_fill<<<EB, 256>>>(ei);                         // 8
    k_gather<<<GB, 256>>>(b_feat, nullptr, 0);       // 9

    // 3 GCN layers, K=128
    for (int i = 0; i < 3; i++) {
        k_fold<<<1, 256>>>(HH, Ws + (size_t)i * HH * HH, bn_g + i * HH, bn_b + i * HH);
        k_gemm_h<<<RB, 256>>>(HH);
        k_gather<<<GB, 256>>>(bs + i * HH, (i == 2) ? out : nullptr, (i == 2) ? 1 : 0);
    }
}

// round 12
// speedup vs baseline: 1.1778x; 1.1778x over previous
#include <cuda_runtime.h>
#include <cuda_fp16.h>
#include <cstdint>

#define NN   50000
#define EE   800000
#define HIN  256
#define HH   128
#define BNEPS 1e-5f

// ---------------- device scratch ----------------
__device__ int    g_degr[NN];
__device__ int    g_cnt[NN];
__device__ int    g_cursor[NN];
__device__ int    g_startv[NN + 1];
__device__ int    g_csr_rows[EE];
__device__ float  g_dinv[NN];
__device__ __half g_s[(size_t)NN * HH];      // pre-aggregation messages (fp16, dinv-scaled)
__device__ __half g_ah[(size_t)NN * HIN];    // A operand hi (fp16)
__device__ __half g_al[(size_t)NN * HIN];    // A operand lo (fp16)
__device__ __half g_w16[HH * HIN];           // folded weight fp16, [n][k] K-major
__device__ float  g_sum[HIN];
__device__ float  g_sumsq[HIN];
__device__ float  g_bshift[HH];

// ---------------- PTX helpers (baseline sm_80+ only) ----------------
__device__ __forceinline__ uint32_t smem_u32(const void* p) {
    uint32_t a;
    asm("{ .reg .u64 t; cvta.to.shared.u64 t, %1; cvt.u32.u64 %0, t; }" : "=r"(a) : "l"(p));
    return a;
}
#define CP16(dst, src) \
    asm volatile("cp.async.cg.shared.global [%0], [%1], 16;" :: "r"(dst), "l"(src))
#define CP_COMMIT() asm volatile("cp.async.commit_group;" ::: "memory")
#define CP_WAIT1()  asm volatile("cp.async.wait_group 1;" ::: "memory")
#define LDSM_X4(r, addr) \
    asm volatile("ldmatrix.sync.aligned.m8n8.x4.shared.b16 {%0,%1,%2,%3}, [%4];" \
        : "=r"((r)[0]), "=r"((r)[1]), "=r"((r)[2]), "=r"((r)[3]) : "r"(addr))
#define MMA_F16(c, a, b) \
    asm volatile("mma.sync.aligned.m16n8k16.row.col.f32.f16.f16.f32 " \
        "{%0,%1,%2,%3}, {%4,%5,%6,%7}, {%8,%9}, {%0,%1,%2,%3};" \
        : "+f"((c)[0]), "+f"((c)[1]), "+f"((c)[2]), "+f"((c)[3]) \
        : "r"((a)[0]), "r"((a)[1]), "r"((a)[2]), "r"((a)[3]), "r"((b)[0]), "r"((b)[1]))

// ---------------- CSR build ----------------
__global__ void k_zero_counts() {
    int i = blockIdx.x * blockDim.x + threadIdx.x;
    if (i < NN) { g_degr[i] = 0; g_cnt[i] = 0; g_cursor[i] = 0; }
}
__global__ void k_count(const int* __restrict__ ei) {
    int e = blockIdx.x * blockDim.x + threadIdx.x;
    if (e < EE) {
        atomicAdd(&g_degr[ei[e]], 1);
        atomicAdd(&g_cnt[ei[EE + e]], 1);
    }
}
__global__ void k_scan() {
    __shared__ int part[1024];
    int t = threadIdx.x;
    const int per = (NN + 1023) / 1024;
    int b = t * per, e = min(b + per, NN);
    int s = 0;
    for (int i = b; i < e; i++) s += g_cnt[i];
    part[t] = s;
    __syncthreads();
    for (int off = 1; off < 1024; off <<= 1) {
        int v = (t >= off) ? part[t - off] : 0;
        __syncthreads();
        part[t] += v;
        __syncthreads();
    }
    int base = (t == 0) ? 0 : part[t - 1];
    for (int i = b; i < e; i++) { g_startv[i] = base; base += g_cnt[i]; }
    if (t == 1023) g_startv[NN] = part[1023];
}
__global__ void k_fill(const int* __restrict__ ei) {
    int e = blockIdx.x * blockDim.x + threadIdx.x;
    if (e < EE) {
        int r = ei[e], c = ei[EE + e];
        int p = atomicAdd(&g_cursor[c], 1);
        g_csr_rows[g_startv[c] + p] = r;
    }
}
__global__ void k_dinv() {
    int i = blockIdx.x * blockDim.x + threadIdx.x;
    if (i < NN) g_dinv[i] = rsqrtf((float)g_degr[i] + 1.0f);
}

// ---------------- BN stats for raw input x (K=256) ----------------
__global__ void k_stats(const float* __restrict__ A, int C) {
    int j = threadIdx.x;
    int r0 = blockIdx.x * 128;
    int rend = min(r0 + 128, NN);
    float s = 0.f, ss = 0.f;
    for (int r = r0; r < rend; r++) {
        float v = A[(size_t)r * C + j];
        s += v; ss += v * v;
    }
    atomicAdd(&g_sum[j], s);
    atomicAdd(&g_sumsq[j], ss);
}

// ---------------- fold BN into weights; emit fp16 W^T + fp32 bshift ----------------
__global__ void k_fold(int K, const float* __restrict__ W,
                       const float* __restrict__ gam, const float* __restrict__ bet) {
    __shared__ float sc[HIN], sh[HIN];
    int t = threadIdx.x;             // 256 threads
    if (t < K) {
        float mu  = g_sum[t] * (1.0f / NN);
        float var = g_sumsq[t] * (1.0f / NN) - mu * mu;
        float a   = rsqrtf(var + BNEPS) * gam[t];
        sc[t] = a;
        sh[t] = bet[t] - mu * a;
    }
    __syncthreads();
    for (int idx = t; idx < K * HH; idx += 256) {
        int k = idx >> 7;            // W row
        int n = idx & 127;           // W col
        g_w16[(size_t)n * K + k] = __float2half_rn(sc[k] * W[idx]);
    }
    if (t < HH) {
        float acc = 0.f;
        for (int k = 0; k < K; k++) acc += sh[k] * W[k * HH + t];
        g_bshift[t] = acc;
    }
    g_sum[t] = 0.f;
    g_sumsq[t] = 0.f;
}

// ---------------- split raw x -> fp16 hi/lo ----------------
__global__ void k_convx(const float* __restrict__ x) {
    size_t i = (size_t)blockIdx.x * blockDim.x + threadIdx.x;   // over NN*HIN/4
    float4 v = ((const float4*)x)[i];
    __half h0 = __float2half_rn(v.x), h1 = __float2half_rn(v.y);
    __half h2 = __float2half_rn(v.z), h3 = __float2half_rn(v.w);
    __half2* ph = (__half2*)g_ah;
    __half2* pl = (__half2*)g_al;
    ph[i * 2 + 0] = __halves2half2(h0, h1);
    ph[i * 2 + 1] = __halves2half2(h2, h3);
    pl[i * 2 + 0] = __floats2half2_rn(v.x - __half2float(h0), v.y - __half2float(h1));
    pl[i * 2 + 1] = __floats2half2_rn(v.z - __half2float(h2), v.w - __half2float(h3));
}

// ---------------- 2-term fp16 HMMA GEMM ----------------
// g_s(fp16) = ((Ah + Al) @ W16^T + bshift) * dinv[row]
#define RS   48
#define TSZ  (128 * RS)          // 6144 bytes per tile
#define STG  (3 * TSZ)           // 18432 bytes per stage

__global__ void __launch_bounds__(256) k_gemm_h(int K) {
    __shared__ char smem[2 * STG];
    const int t    = threadIdx.x;
    const int wid  = t >> 5;
    const int lane = t & 31;
    const int wm   = wid & 3;          // 32-row band
    const int wn   = wid >> 2;         // 64-col band
    const int row0 = blockIdx.x * 128;
    const uint32_t sbase = smem_u32(smem);

    float c[2][8][4];
    #pragma unroll
    for (int mt = 0; mt < 2; mt++)
        #pragma unroll
        for (int nt = 0; nt < 8; nt++)
            #pragma unroll
            for (int q = 0; q < 4; q++) c[mt][nt][q] = 0.f;

    const int lr = t >> 1;
    const int lh = t & 1;
    const int ar = min(row0 + lr, NN - 1);
    const uint32_t so = lr * RS + lh * 16;
    const int nch = K >> 4;

    {
        size_t ka = (size_t)ar * K + lh * 8;
        size_t kb = (size_t)lr * K + lh * 8;
        CP16(sbase + 0 * TSZ + so, g_ah + ka);
        CP16(sbase + 1 * TSZ + so, g_al + ka);
        CP16(sbase + 2 * TSZ + so, g_w16 + kb);
    }
    CP_COMMIT();

    for (int kc = 0; kc < nch; kc++) {
        if (kc + 1 < nch) {
            uint32_t sb = sbase + ((kc + 1) & 1) * STG;
            size_t ka = (size_t)ar * K + (kc + 1) * 16 + lh * 8;
            size_t kb = (size_t)lr * K + (kc + 1) * 16 + lh * 8;
            CP16(sb + 0 * TSZ + so, g_ah + ka);
            CP16(sb + 1 * TSZ + so, g_al + ka);
            CP16(sb + 2 * TSZ + so, g_w16 + kb);
        }
        CP_COMMIT();
        CP_WAIT1();
        __syncthreads();

        uint32_t base = sbase + (kc & 1) * STG;
        uint32_t ah[2][4], al[2][4];
        #pragma unroll
        for (int mt = 0; mt < 2; mt++) {
            uint32_t addr = base + (wm * 32 + mt * 16 + (lane & 15)) * RS + (lane >> 4) * 16;
            LDSM_X4(ah[mt], addr);
            LDSM_X4(al[mt], addr + TSZ);
        }
        uint32_t bw[8][2];
        #pragma unroll
        for (int p = 0; p < 4; p++) {
            uint32_t addr = base + 2 * TSZ + (wn * 64 + p * 16 + (lane & 15)) * RS + (lane >> 4) * 16;
            uint32_t rr[4];
            LDSM_X4(rr, addr);
            bw[2 * p][0] = rr[0]; bw[2 * p][1] = rr[2];
            bw[2 * p + 1][0] = rr[1]; bw[2 * p + 1][1] = rr[3];
        }
        #pragma unroll
        for (int mt = 0; mt < 2; mt++)
            #pragma unroll
            for (int nt = 0; nt < 8; nt++) {
                MMA_F16(c[mt][nt], ah[mt], bw[nt]);
                MMA_F16(c[mt][nt], al[mt], bw[nt]);
            }
        __syncthreads();
    }

    // epilogue: (acc + bshift[col]) * dinv[row] -> fp16 g_s
    float bsv[8][2];
    #pragma unroll
    for (int nt = 0; nt < 8; nt++) {
        int gc = wn * 64 + nt * 8 + (lane & 3) * 2;
        bsv[nt][0] = __ldg(&g_bshift[gc]);
        bsv[nt][1] = __ldg(&g_bshift[gc + 1]);
    }
    #pragma unroll
    for (int mt = 0; mt < 2; mt++) {
        int r0g = row0 + wm * 32 + mt * 16 + (lane >> 2);
        int r1g = r0g + 8;
        float dv0 = g_dinv[min(r0g, NN - 1)];
        float dv1 = g_dinv[min(r1g, NN - 1)];
        #pragma unroll
        for (int nt = 0; nt < 8; nt++) {
            int gc = wn * 64 + nt * 8 + (lane & 3) * 2;
            if (r0g < NN)
                *(__half2*)(g_s + (size_t)r0g * HH + gc) =
                    __floats2half2_rn((c[mt][nt][0] + bsv[nt][0]) * dv0,
                                      (c[mt][nt][1] + bsv[nt][1]) * dv0);
            if (r1g < NN)
                *(__half2*)(g_s + (size_t)r1g * HH + gc) =
                    __floats2half2_rn((c[mt][nt][2] + bsv[nt][0]) * dv1,
                                      (c[mt][nt][3] + bsv[nt][1]) * dv1);
        }
    }
}

// ---------------- gather: half-warp per node, uint4/lane, 2-edge unroll ----------------
__device__ __forceinline__ void add8(float* a, uint4 v) {
    float2 p;
    p = __half22float2(*(__half2*)&v.x); a[0] += p.x; a[1] += p.y;
    p = __half22float2(*(__half2*)&v.y); a[2] += p.x; a[3] += p.y;
    p = __half22float2(*(__half2*)&v.z); a[4] += p.x; a[5] += p.y;
    p = __half22float2(*(__half2*)&v.w); a[6] += p.x; a[7] += p.y;
}

__global__ void __launch_bounds__(256) k_gather(const float* __restrict__ bgcn,
                                                float* __restrict__ out, int final_layer) {
    const int lane = threadIdx.x & 31;
    const int half = lane >> 4;          // 0/1 -> which node of the pair
    const int l16  = lane & 15;          // 16B slot within the 256B row
    const int wg   = (blockIdx.x * blockDim.x + threadIdx.x) >> 5;
    const int nw   = (gridDim.x * blockDim.x) >> 5;
    __shared__ float sS[128], sQ[128];
    if (threadIdx.x < 128) { sS[threadIdx.x] = 0.f; sQ[threadIdx.x] = 0.f; }
    __syncthreads();

    const uint4* __restrict__ s4 = (const uint4*)g_s;   // 16 uint4 per node row
    float bv[8];
    #pragma unroll
    for (int i = 0; i < 8; i++) bv[i] = __ldg(&bgcn[l16 * 8 + i]);
    float stS[8], stQ[8];
    #pragma unroll
    for (int i = 0; i < 8; i++) { stS[i] = 0.f; stQ[i] = 0.f; }

    for (int n0 = wg * 2; n0 < NN; n0 += nw * 2) {
        int node = n0 + half;
        bool act = node < NN;
        int nc = act ? node : NN - 1;
        int beg = g_startv[nc];
        int end = act ? g_startv[nc + 1] : beg;
        int deg = end - beg;
        int mdeg = max(deg, __shfl_xor_sync(0xFFFFFFFFu, deg, 16));

        float a[8];
        {   // self-loop term (already dinv-scaled in g_s)
            uint4 v = s4[(size_t)nc * 16 + l16];
            float2 p;
            p = __half22float2(*(__half2*)&v.x); a[0] = p.x; a[1] = p.y;
            p = __half22float2(*(__half2*)&v.y); a[2] = p.x; a[3] = p.y;
            p = __half22float2(*(__half2*)&v.z); a[4] = p.x; a[5] = p.y;
            p = __half22float2(*(__half2*)&v.w); a[6] = p.x; a[7] = p.y;
        }

        int k = beg;
        for (int it = 0; it < mdeg; it += 2) {
            bool e0 = k < end, e1 = (k + 1) < end;
            int r0 = __ldg(&g_csr_rows[min(k, EE - 1)]);
            int r1 = __ldg(&g_csr_rows[min(k + 1, EE - 1)]);
            uint4 w0 = make_uint4(0u, 0u, 0u, 0u);
            uint4 w1 = make_uint4(0u, 0u, 0u, 0u);
            if (e0) w0 = s4[(size_t)r0 * 16 + l16];
            if (e1) w1 = s4[(size_t)r1 * 16 + l16];
            add8(a, w0);     // zero bits -> +0.0, safe when inactive
            add8(a, w1);
            k += 2;
        }

        float dvn = g_dinv[nc];
        float o[8];
        #pragma unroll
        for (int i = 0; i < 8; i++) o[i] = a[i] * dvn + bv[i];

        if (act) {
            size_t base = (size_t)node * HH + l16 * 8;
            if (final_layer) {
                float4 v0 = make_float4(o[0], o[1], o[2], o[3]);
                float4 v1 = make_float4(o[4], o[5], o[6], o[7]);
                *(float4*)(out + base)     = v0;
                *(float4*)(out + base + 4) = v1;
            } else {
                __half h[8];
                #pragma unroll
                for (int i = 0; i < 8; i++) h[i] = __float2half_rn(o[i]);
                uint4 uh, ul;
                *(__half2*)&uh.x = __halves2half2(h[0], h[1]);
                *(__half2*)&uh.y = __halves2half2(h[2], h[3]);
                *(__half2*)&uh.z = __halves2half2(h[4], h[5]);
                *(__half2*)&uh.w = __halves2half2(h[6], h[7]);
                *(__half2*)&ul.x = __floats2half2_rn(o[0] - __half2float(h[0]), o[1] - __half2float(h[1]));
                *(__half2*)&ul.y = __floats2half2_rn(o[2] - __half2float(h[2]), o[3] - __half2float(h[3]));
                *(__half2*)&ul.z = __floats2half2_rn(o[4] - __half2float(h[4]), o[5] - __half2float(h[5]));
                *(__half2*)&ul.w = __floats2half2_rn(o[6] - __half2float(h[6]), o[7] - __half2float(h[7]));
                *(uint4*)(g_ah + base) = uh;
                *(uint4*)(g_al + base) = ul;
                #pragma unroll
                for (int i = 0; i < 8; i++) {
                    stS[i] += o[i];
                    stQ[i] += o[i] * o[i];
                }
            }
        }
    }

    if (!final_layer) {
        #pragma unroll
        for (int i = 0; i < 8; i++) {
            atomicAdd(&sS[l16 * 8 + i], stS[i]);
            atomicAdd(&sQ[l16 * 8 + i], stQ[i]);
        }
        __syncthreads();
        if (threadIdx.x < 128) {
            atomicAdd(&g_sum[threadIdx.x], sS[threadIdx.x]);
            atomicAdd(&g_sumsq[threadIdx.x], sQ[threadIdx.x]);
        }
    }
}

// ---------------- launch ----------------
extern "C" void kernel_launch(void* const* d_in, const int* in_sizes, int n_in,
                              void* d_out, int out_size) {
    const float* x       = (const float*)d_in[0];
    const int*   ei      = (const int*)  d_in[1];
    const float* bnf_g   = (const float*)d_in[2];
    const float* bnf_b   = (const float*)d_in[3];
    const float* W_feat  = (const float*)d_in[4];
    const float* b_feat  = (const float*)d_in[5];
    const float* bn_g    = (const float*)d_in[6];
    const float* bn_b    = (const float*)d_in[7];
    const float* Ws      = (const float*)d_in[8];
    const float* bs      = (const float*)d_in[9];
    float* out = (float*)d_out;

    const int RB = (NN + 127) / 128;              // 391 tiles
    const int GB = 1563;                          // gather: 12504 warps x 2 nodes
    const int EB = (EE + 255) / 256;

    // CSR chain (dinv before GEMM: epilogue scaling needs it)
    k_zero_counts<<<(NN + 255) / 256, 256>>>();      // 0
    k_count<<<EB, 256>>>(ei);                        // 1
    k_dinv<<<(NN + 255) / 256, 256>>>();             // 2
    k_stats<<<RB, HIN>>>(x, HIN);                    // 3
    k_fold<<<1, 256>>>(HIN, W_feat, bnf_g, bnf_b);   // 4
    k_convx<<<(NN * HIN / 4 + 255) / 256, 256>>>(x); // 5
    k_gemm_h<<<RB, 256>>>(HIN);                      // 6
    k_scan<<<1, 1024>>>();                           // 7
    k_fill<<<EB, 256>>>(ei);                         // 8
    k_gather<<<GB, 256>>>(b_feat, nullptr, 0);       // 9

    // 3 GCN layers, K=128
    for (int i = 0; i < 3; i++) {
        k_fold<<<1, 256>>>(HH, Ws + (size_t)i * HH * HH, bn_g + i * HH, bn_b + i * HH);
        k_gemm_h<<<RB, 256>>>(HH);
        k_gather<<<GB, 256>>>(bs + i * HH, (i == 2) ? out : nullptr, (i == 2) ? 1 : 0);
    }
}

// round 13
// speedup vs baseline: 1.3872x; 1.1778x over previous
#include <cuda_runtime.h>
#include <cuda_fp16.h>
#include <cstdint>

#define NN   50000
#define EE   800000
#define HIN  256
#define HH   128
#define BNEPS 1e-5f

// ---------------- device scratch ----------------
__device__ int    g_degr[NN];
__device__ int    g_cnt[NN];
__device__ int    g_cursor[NN];
__device__ int    g_startv[NN + 1];
__device__ int    g_csr_rows[EE];
__device__ float  g_dinv[NN];
__device__ __half g_s[(size_t)NN * HH];      // pre-aggregation messages (fp16, dinv-scaled)
__device__ __half g_ah[(size_t)NN * HIN];    // A operand hi (fp16)
__device__ __half g_al[(size_t)NN * HIN];    // A operand lo (fp16)
__device__ __half g_w16[HH * HIN];           // folded weight fp16, [n][k] K-major
__device__ float  g_sum[HIN];
__device__ float  g_sumsq[HIN];
__device__ float  g_bshift[HH];

// ---------------- PTX helpers (baseline sm_80+ only) ----------------
__device__ __forceinline__ uint32_t smem_u32(const void* p) {
    uint32_t a;
    asm("{ .reg .u64 t; cvta.to.shared.u64 t, %1; cvt.u32.u64 %0, t; }" : "=r"(a) : "l"(p));
    return a;
}
#define CP16(dst, src) \
    asm volatile("cp.async.cg.shared.global [%0], [%1], 16;" :: "r"(dst), "l"(src))
#define CP_COMMIT() asm volatile("cp.async.commit_group;" ::: "memory")
#define CP_WAIT1()  asm volatile("cp.async.wait_group 1;" ::: "memory")
#define LDSM_X4(r, addr) \
    asm volatile("ldmatrix.sync.aligned.m8n8.x4.shared.b16 {%0,%1,%2,%3}, [%4];" \
        : "=r"((r)[0]), "=r"((r)[1]), "=r"((r)[2]), "=r"((r)[3]) : "r"(addr))
#define MMA_F16(c, a, b) \
    asm volatile("mma.sync.aligned.m16n8k16.row.col.f32.f16.f16.f32 " \
        "{%0,%1,%2,%3}, {%4,%5,%6,%7}, {%8,%9}, {%0,%1,%2,%3};" \
        : "+f"((c)[0]), "+f"((c)[1]), "+f"((c)[2]), "+f"((c)[3]) \
        : "r"((a)[0]), "r"((a)[1]), "r"((a)[2]), "r"((a)[3]), "r"((b)[0]), "r"((b)[1]))

// ---------------- CSR build ----------------
__global__ void k_count(const int* __restrict__ ei) {
    int e = blockIdx.x * blockDim.x + threadIdx.x;
    if (e < EE) {
        atomicAdd(&g_degr[ei[e]], 1);
        atomicAdd(&g_cnt[ei[EE + e]], 1);
    }
}
__global__ void k_scan() {
    __shared__ int part[1024];
    int t = threadIdx.x;
    const int per = (NN + 1023) / 1024;
    int b = t * per, e = min(b + per, NN);
    int s = 0;
    for (int i = b; i < e; i++) s += g_cnt[i];
    part[t] = s;
    __syncthreads();
    for (int off = 1; off < 1024; off <<= 1) {
        int v = (t >= off) ? part[t - off] : 0;
        __syncthreads();
        part[t] += v;
        __syncthreads();
    }
    int base = (t == 0) ? 0 : part[t - 1];
    for (int i = b; i < e; i++) { g_startv[i] = base; base += g_cnt[i]; }
    if (t == 1023) g_startv[NN] = part[1023];
}
__global__ void k_fill(const int* __restrict__ ei) {
    int e = blockIdx.x * blockDim.x + threadIdx.x;
    if (e < EE) {
        int r = ei[e], c = ei[EE + e];
        int p = atomicAdd(&g_cursor[c], 1);
        g_csr_rows[g_startv[c] + p] = r;
    }
}
__global__ void k_dinv() {
    int i = blockIdx.x * blockDim.x + threadIdx.x;
    if (i < NN) g_dinv[i] = rsqrtf((float)g_degr[i] + 1.0f);
}

// ---------------- fused: convert x -> fp16 hi/lo, BN col stats, zero CSR arrays ----------------
__global__ void __launch_bounds__(256) k_convx_stats(const float* __restrict__ x) {
    __shared__ float sS[HIN], sQ[HIN];
    const int t = threadIdx.x;              // 256
    sS[t] = 0.f; sQ[t] = 0.f;
    __syncthreads();

    const int col = (t & 63) * 4;           // fixed 4 columns per thread
    const int ro  = t >> 6;                 // row offset 0..3
    float s0 = 0.f, s1 = 0.f, s2 = 0.f, s3 = 0.f;
    float q0 = 0.f, q1 = 0.f, q2 = 0.f, q3 = 0.f;

    for (int r0 = blockIdx.x * 4; r0 < NN; r0 += gridDim.x * 4) {
        int r = r0 + ro;                    // NN % 4 == 0 -> always < NN
        size_t idx = (size_t)r * HIN + col;
        float4 v = *(const float4*)(x + idx);
        __half h0 = __float2half_rn(v.x), h1 = __float2half_rn(v.y);
        __half h2 = __float2half_rn(v.z), h3 = __float2half_rn(v.w);
        uint2 uh, ul;
        *(__half2*)&uh.x = __halves2half2(h0, h1);
        *(__half2*)&uh.y = __halves2half2(h2, h3);
        *(__half2*)&ul.x = __floats2half2_rn(v.x - __half2float(h0), v.y - __half2float(h1));
        *(__half2*)&ul.y = __floats2half2_rn(v.z - __half2float(h2), v.w - __half2float(h3));
        *(uint2*)(g_ah + idx) = uh;
        *(uint2*)(g_al + idx) = ul;
        s0 += v.x; q0 += v.x * v.x;
        s1 += v.y; q1 += v.y * v.y;
        s2 += v.z; q2 += v.z * v.z;
        s3 += v.w; q3 += v.w * v.w;
    }
    atomicAdd(&sS[col + 0], s0); atomicAdd(&sQ[col + 0], q0);
    atomicAdd(&sS[col + 1], s1); atomicAdd(&sQ[col + 1], q1);
    atomicAdd(&sS[col + 2], s2); atomicAdd(&sQ[col + 2], q2);
    atomicAdd(&sS[col + 3], s3); atomicAdd(&sQ[col + 3], q3);
    __syncthreads();
    atomicAdd(&g_sum[t], sS[t]);
    atomicAdd(&g_sumsq[t], sQ[t]);

    // fused zeroing of CSR count arrays
    for (int i = blockIdx.x * blockDim.x + t; i < NN; i += gridDim.x * blockDim.x) {
        g_degr[i] = 0; g_cnt[i] = 0; g_cursor[i] = 0;
    }
}

// ---------------- fold BN into weights; emit fp16 W^T + fp32 bshift ----------------
__global__ void k_fold(int K, const float* __restrict__ W,
                       const float* __restrict__ gam, const float* __restrict__ bet) {
    __shared__ float sc[HIN], sh[HIN];
    int t = threadIdx.x;             // 256 threads
    if (t < K) {
        float mu  = g_sum[t] * (1.0f / NN);
        float var = g_sumsq[t] * (1.0f / NN) - mu * mu;
        float a   = rsqrtf(var + BNEPS) * gam[t];
        sc[t] = a;
        sh[t] = bet[t] - mu * a;
    }
    __syncthreads();
    for (int idx = t; idx < K * HH; idx += 256) {
        int k = idx >> 7;            // W row
        int n = idx & 127;           // W col
        g_w16[(size_t)n * K + k] = __float2half_rn(sc[k] * W[idx]);
    }
    if (t < HH) {
        float acc = 0.f;
        for (int k = 0; k < K; k++) acc += sh[k] * W[k * HH + t];
        g_bshift[t] = acc;
    }
    g_sum[t] = 0.f;
    g_sumsq[t] = 0.f;
}

// ---------------- 2-term fp16 HMMA GEMM ----------------
// g_s(fp16) = ((Ah + Al) @ W16^T + bshift) * dinv[row]
#define RS   48
#define TSZ  (128 * RS)          // 6144 bytes per tile
#define STG  (3 * TSZ)           // 18432 bytes per stage

__global__ void __launch_bounds__(256) k_gemm_h(int K) {
    __shared__ char smem[2 * STG];
    const int t    = threadIdx.x;
    const int wid  = t >> 5;
    const int lane = t & 31;
    const int wm   = wid & 3;          // 32-row band
    const int wn   = wid >> 2;         // 64-col band
    const int row0 = blockIdx.x * 128;
    const uint32_t sbase = smem_u32(smem);

    float c[2][8][4];
    #pragma unroll
    for (int mt = 0; mt < 2; mt++)
        #pragma unroll
        for (int nt = 0; nt < 8; nt++)
            #pragma unroll
            for (int q = 0; q < 4; q++) c[mt][nt][q] = 0.f;

    const int lr = t >> 1;
    const int lh = t & 1;
    const int ar = min(row0 + lr, NN - 1);
    const uint32_t so = lr * RS + lh * 16;
    const int nch = K >> 4;

    {
        size_t ka = (size_t)ar * K + lh * 8;
        size_t kb = (size_t)lr * K + lh * 8;
        CP16(sbase + 0 * TSZ + so, g_ah + ka);
        CP16(sbase + 1 * TSZ + so, g_al + ka);
        CP16(sbase + 2 * TSZ + so, g_w16 + kb);
    }
    CP_COMMIT();

    for (int kc = 0; kc < nch; kc++) {
        if (kc + 1 < nch) {
            uint32_t sb = sbase + ((kc + 1) & 1) * STG;
            size_t ka = (size_t)ar * K + (kc + 1) * 16 + lh * 8;
            size_t kb = (size_t)lr * K + (kc + 1) * 16 + lh * 8;
            CP16(sb + 0 * TSZ + so, g_ah + ka);
            CP16(sb + 1 * TSZ + so, g_al + ka);
            CP16(sb + 2 * TSZ + so, g_w16 + kb);
        }
        CP_COMMIT();
        CP_WAIT1();
        __syncthreads();

        uint32_t base = sbase + (kc & 1) * STG;
        uint32_t ah[2][4], al[2][4];
        #pragma unroll
        for (int mt = 0; mt < 2; mt++) {
            uint32_t addr = base + (wm * 32 + mt * 16 + (lane & 15)) * RS + (lane >> 4) * 16;
            LDSM_X4(ah[mt], addr);
            LDSM_X4(al[mt], addr + TSZ);
        }
        uint32_t bw[8][2];
        #pragma unroll
        for (int p = 0; p < 4; p++) {
            uint32_t addr = base + 2 * TSZ + (wn * 64 + p * 16 + (lane & 15)) * RS + (lane >> 4) * 16;
            uint32_t rr[4];
            LDSM_X4(rr, addr);
            bw[2 * p][0] = rr[0]; bw[2 * p][1] = rr[2];
            bw[2 * p + 1][0] = rr[1]; bw[2 * p + 1][1] = rr[3];
        }
        #pragma unroll
        for (int mt = 0; mt < 2; mt++)
            #pragma unroll
            for (int nt = 0; nt < 8; nt++) {
                MMA_F16(c[mt][nt], ah[mt], bw[nt]);
                MMA_F16(c[mt][nt], al[mt], bw[nt]);
            }
        __syncthreads();
    }

    // epilogue: (acc + bshift[col]) * dinv[row] -> fp16 g_s
    float bsv[8][2];
    #pragma unroll
    for (int nt = 0; nt < 8; nt++) {
        int gc = wn * 64 + nt * 8 + (lane & 3) * 2;
        bsv[nt][0] = __ldg(&g_bshift[gc]);
        bsv[nt][1] = __ldg(&g_bshift[gc + 1]);
    }
    #pragma unroll
    for (int mt = 0; mt < 2; mt++) {
        int r0g = row0 + wm * 32 + mt * 16 + (lane >> 2);
        int r1g = r0g + 8;
        float dv0 = g_dinv[min(r0g, NN - 1)];
        float dv1 = g_dinv[min(r1g, NN - 1)];
        #pragma unroll
        for (int nt = 0; nt < 8; nt++) {
            int gc = wn * 64 + nt * 8 + (lane & 3) * 2;
            if (r0g < NN)
                *(__half2*)(g_s + (size_t)r0g * HH + gc) =
                    __floats2half2_rn((c[mt][nt][0] + bsv[nt][0]) * dv0,
                                      (c[mt][nt][1] + bsv[nt][1]) * dv0);
            if (r1g < NN)
                *(__half2*)(g_s + (size_t)r1g * HH + gc) =
                    __floats2half2_rn((c[mt][nt][2] + bsv[nt][0]) * dv1,
                                      (c[mt][nt][3] + bsv[nt][1]) * dv1);
        }
    }
}

// ---------------- gather: warp-per-node, uint2/lane, 4-edge unroll with HADD2 pair-tree ----------------
__global__ void __launch_bounds__(256) k_gather(const float* __restrict__ bgcn,
                                                float* __restrict__ out, int final_layer) {
    const int lane = threadIdx.x & 31;
    const int wg   = (blockIdx.x * blockDim.x + threadIdx.x) >> 5;
    const int nw   = (gridDim.x * blockDim.x) >> 5;
    __shared__ float sS[128], sQ[128];
    if (threadIdx.x < 128) { sS[threadIdx.x] = 0.f; sQ[threadIdx.x] = 0.f; }
    __syncthreads();

    const uint2* __restrict__ s2 = (const uint2*)g_s;   // 32 uint2 per node row
    float4 b = *(const float4*)(bgcn + lane * 4);
    float4 stS = make_float4(0.f, 0.f, 0.f, 0.f);
    float4 stQ = make_float4(0.f, 0.f, 0.f, 0.f);

    for (int node = wg; node < NN; node += nw) {
        uint2 vs = s2[(size_t)node * 32 + lane];        // self-loop (dinv-scaled)
        float2 f0 = __half22float2(*(__half2*)&vs.x);
        float2 f1 = __half22float2(*(__half2*)&vs.y);
        float a0 = f0.x, a1 = f0.y, a2 = f1.x, a3 = f1.y;

        int beg = g_startv[node];
        int end = g_startv[node + 1];
        int k = beg;
        for (; k + 3 < end; k += 4) {
            int r0 = __ldg(&g_csr_rows[k]);
            int r1 = __ldg(&g_csr_rows[k + 1]);
            int r2 = __ldg(&g_csr_rows[k + 2]);
            int r3 = __ldg(&g_csr_rows[k + 3]);
            uint2 v0 = s2[(size_t)r0 * 32 + lane];
            uint2 v1 = s2[(size_t)r1 * 32 + lane];
            uint2 v2 = s2[(size_t)r2 * 32 + lane];
            uint2 v3 = s2[(size_t)r3 * 32 + lane];
            __half2 p0 = __hadd2(*(__half2*)&v0.x, *(__half2*)&v1.x);
            __half2 p1 = __hadd2(*(__half2*)&v0.y, *(__half2*)&v1.y);
            __half2 p2 = __hadd2(*(__half2*)&v2.x, *(__half2*)&v3.x);
            __half2 p3 = __hadd2(*(__half2*)&v2.y, *(__half2*)&v3.y);
            float2 q;
            q = __half22float2(p0); a0 += q.x; a1 += q.y;
            q = __half22float2(p1); a2 += q.x; a3 += q.y;
            q = __half22float2(p2); a0 += q.x; a1 += q.y;
            q = __half22float2(p3); a2 += q.x; a3 += q.y;
        }
        if (k + 1 < end) {
            int r0 = __ldg(&g_csr_rows[k]);
            int r1 = __ldg(&g_csr_rows[k + 1]);
            uint2 v0 = s2[(size_t)r0 * 32 + lane];
            uint2 v1 = s2[(size_t)r1 * 32 + lane];
            __half2 p0 = __hadd2(*(__half2*)&v0.x, *(__half2*)&v1.x);
            __half2 p1 = __hadd2(*(__half2*)&v0.y, *(__half2*)&v1.y);
            float2 q;
            q = __half22float2(p0); a0 += q.x; a1 += q.y;
            q = __half22float2(p1); a2 += q.x; a3 += q.y;
            k += 2;
        }
        if (k < end) {
            int r0 = __ldg(&g_csr_rows[k]);
            uint2 v0 = s2[(size_t)r0 * 32 + lane];
            float2 q;
            q = __half22float2(*(__half2*)&v0.x); a0 += q.x; a1 += q.y;
            q = __half22float2(*(__half2*)&v0.y); a2 += q.x; a3 += q.y;
        }

        float dvn = g_dinv[node];
        float4 o;
        o.x = a0 * dvn + b.x;
        o.y = a1 * dvn + b.y;
        o.z = a2 * dvn + b.z;
        o.w = a3 * dvn + b.w;

        if (final_layer) {
            *(float4*)(out + (size_t)node * HH + lane * 4) = o;
        } else {
            __half h0 = __float2half_rn(o.x), h1 = __float2half_rn(o.y);
            __half h2 = __float2half_rn(o.z), h3 = __float2half_rn(o.w);
            size_t base = (size_t)node * HH + lane * 4;
            uint2 uh, ul;
            *(__half2*)&uh.x = __halves2half2(h0, h1);
            *(__half2*)&uh.y = __halves2half2(h2, h3);
            *(__half2*)&ul.x = __floats2half2_rn(o.x - __half2float(h0), o.y - __half2float(h1));
            *(__half2*)&ul.y = __floats2half2_rn(o.z - __half2float(h2), o.w - __half2float(h3));
            *(uint2*)(g_ah + base) = uh;
            *(uint2*)(g_al + base) = ul;
            stS.x += o.x; stS.y += o.y; stS.z += o.z; stS.w += o.w;
            stQ.x += o.x * o.x; stQ.y += o.y * o.y;
            stQ.z += o.z * o.z; stQ.w += o.w * o.w;
        }
    }

    if (!final_layer) {
        atomicAdd(&sS[lane * 4 + 0], stS.x);
        atomicAdd(&sS[lane * 4 + 1], stS.y);
        atomicAdd(&sS[lane * 4 + 2], stS.z);
        atomicAdd(&sS[lane * 4 + 3], stS.w);
        atomicAdd(&sQ[lane * 4 + 0], stQ.x);
        atomicAdd(&sQ[lane * 4 + 1], stQ.y);
        atomicAdd(&sQ[lane * 4 + 2], stQ.z);
        atomicAdd(&sQ[lane * 4 + 3], stQ.w);
        __syncthreads();
        if (threadIdx.x < 128) {
            atomicAdd(&g_sum[threadIdx.x], sS[threadIdx.x]);
            atomicAdd(&g_sumsq[threadIdx.x], sQ[threadIdx.x]);
        }
    }
}

// ---------------- launch ----------------
extern "C" void kernel_launch(void* const* d_in, const int* in_sizes, int n_in,
                              void* d_out, int out_size) {
    const float* x       = (const float*)d_in[0];
    const int*   ei      = (const int*)  d_in[1];
    const float* bnf_g   = (const float*)d_in[2];
    const float* bnf_b   = (const float*)d_in[3];
    const float* W_feat  = (const float*)d_in[4];
    const float* b_feat  = (const float*)d_in[5];
    const float* bn_g    = (const float*)d_in[6];
    const float* bn_b    = (const float*)d_in[7];
    const float* Ws      = (const float*)d_in[8];
    const float* bs      = (const float*)d_in[9];
    float* out = (float*)d_out;

    const int RB = (NN + 127) / 128;              // 391 tiles
    const int GB = 1563;                          // gather: ~12.5k warps, ~4 nodes/warp
    const int EB = (EE + 255) / 256;

    k_convx_stats<<<RB, 256>>>(x);                   // 0: x->fp16 hi/lo + BN stats + zero CSR
    k_fold<<<1, 256>>>(HIN, W_feat, bnf_g, bnf_b);   // 1
    k_count<<<EB, 256>>>(ei);                        // 2
    k_dinv<<<(NN + 255) / 256, 256>>>();             // 3
    k_gemm_h<<<RB, 256>>>(HIN);                      // 4
    k_scan<<<1, 1024>>>();                           // 5
    k_fill<<<EB, 256>>>(ei);                         // 6
    k_gather<<<GB, 256>>>(b_feat, nullptr, 0);       // 7

    // 3 GCN layers, K=128
    for (int i = 0; i < 3; i++) {
        k_fold<<<1, 256>>>(HH, Ws + (size_t)i * HH * HH, bn_g + i * HH, bn_b + i * HH);
        k_gemm_h<<<RB, 256>>>(HH);
        k_gather<<<GB, 256>>>(bs + i * HH, (i == 2) ? out : nullptr, (i == 2) ? 1 : 0);
    }
}